// round 15
// baseline (speedup 1.0000x reference)
#include <cuda_runtime.h>
#include <cstdint>

// Problem constants
#define NB     16
#define NFREQ  513
#define NT     4000
#define NFFT   1024
#define HOP    256
#define OUT_PER_B (3999 * 256)   // 1023744

#define THREADS 256
#define G_HOPS  11               // output hops per block
#define NFRAMES 14               // frames per block (11 + 3 halo)
#define CHUNK   (G_HOPS * HOP)   // 2816
#define NCHUNK  ((OUT_PER_B + CHUNK - 1) / CHUNK)   // 364

#define ROW     1156             // unified frame row stride (floats), 1156%32==4
#define ZBLK8   18               // words per 8-complex Z block (even -> float2 aligned)

// parity-preserving skew for sample layout
#define SKEW(n) ((n) + (((n) >> 6) << 1))

// SMEM layout (floats)
#define SM_FBUF 0
#define SM_TW   (SM_FBUF + NFRAMES * ROW)           // 16184
#define SM_WIN  (SM_TW + 1024)                      // 17208
#define SM_IENV (SM_WIN + 1056)                     // 18264
#define SM_FLOATS (SM_IENV + 256)                   // 18520
#define SMEM_BYTES (SM_FLOATS * 4)                  // 74080 B -> 3 blocks/SM

// Twiddle table e^{+2*pi*i*j/1024}, j = 0..511
__device__ float2 g_tw[512];

// e^{+2*pi*i*j/32}
__constant__ float W32C[32] = {
     1.000000000f,  0.980785280f,  0.923879533f,  0.831469612f,
     0.707106781f,  0.555570233f,  0.382683432f,  0.195090322f,
     0.000000000f, -0.195090322f, -0.382683432f, -0.555570233f,
    -0.707106781f, -0.831469612f, -0.923879533f, -0.980785280f,
    -1.000000000f, -0.980785280f, -0.923879533f, -0.831469612f,
    -0.707106781f, -0.555570233f, -0.382683432f, -0.195090322f,
     0.000000000f,  0.195090322f,  0.382683432f,  0.555570233f,
     0.707106781f,  0.831469612f,  0.923879533f,  0.980785280f
};
__constant__ float W32S[32] = {
     0.000000000f,  0.195090322f,  0.382683432f,  0.555570233f,
     0.707106781f,  0.831469612f,  0.923879533f,  0.980785280f,
     1.000000000f,  0.980785280f,  0.923879533f,  0.831469612f,
     0.707106781f,  0.555570233f,  0.382683432f,  0.195090322f,
     0.000000000f, -0.195090322f, -0.382683432f, -0.555570233f,
    -0.707106781f, -0.831469612f, -0.923879533f, -0.980785280f,
    -1.000000000f, -0.980785280f, -0.923879533f, -0.831469612f,
    -0.707106781f, -0.555570233f, -0.382683432f, -0.195090322f
};

__constant__ int BR3[8] = {0, 4, 2, 6, 1, 5, 3, 7};

__global__ void tw_init_kernel() {
    int j = blockIdx.x * 256 + threadIdx.x;
    if (j < 512) {
        float s, c;
        sincospif((float)j * (1.0f / 512.0f), &s, &c);   // 2*pi*j/1024
        g_tw[j] = make_float2(c, s);
    }
}

__device__ __forceinline__ float2 cmul(float2 a, float2 b) {
    return make_float2(a.x * b.x - a.y * b.y, a.x * b.y + a.y * b.x);
}

// ---------------------------------------------------------------------------
// In-place 8-pt inverse DIF FFT. Output reg r holds Y[bitrev3(r)].
// Y[m] = sum_j v[j] e^{+2*pi*i*j*m/8}
// ---------------------------------------------------------------------------
__device__ __forceinline__ void ifft8_dif(float2 v[8]) {
    // stage 1: h=4, twiddle e^{+2*pi*i*j/8} = W32[4j]
#pragma unroll
    for (int j = 0; j < 4; j++) {
        float2 u = v[j], t = v[j + 4];
        v[j] = make_float2(u.x + t.x, u.y + t.y);
        float dx = u.x - t.x, dy = u.y - t.y;
        float wc = W32C[4 * j], ws = W32S[4 * j];
        v[j + 4] = make_float2(dx * wc - dy * ws, dx * ws + dy * wc);
    }
    // stage 2: h=2, twiddles 1, +i
#pragma unroll
    for (int g = 0; g < 8; g += 4) {
        {
            float2 u = v[g], t = v[g + 2];
            v[g]     = make_float2(u.x + t.x, u.y + t.y);
            v[g + 2] = make_float2(u.x - t.x, u.y - t.y);
        }
        {
            float2 u = v[g + 1], t = v[g + 3];
            v[g + 1] = make_float2(u.x + t.x, u.y + t.y);
            float dx = u.x - t.x, dy = u.y - t.y;
            v[g + 3] = make_float2(-dy, dx);          // * (+i)
        }
    }
    // stage 3: h=1
#pragma unroll
    for (int g = 0; g < 8; g += 2) {
        float2 u = v[g], t = v[g + 1];
        v[g]     = make_float2(u.x + t.x, u.y + t.y);
        v[g + 1] = make_float2(u.x - t.x, u.y - t.y);
    }
}

// ---------------------------------------------------------------------------
// Fused kernel. grid = (NCHUNK, NB), block = 256 (8 warps), 3 blocks/SM.
// Each frame's 512-pt IFFT is split across a warp PAIR (64 lanes, 8 cplx each).
// ---------------------------------------------------------------------------
__global__ void __launch_bounds__(THREADS, 3)
istft_fused_kernel(const float* __restrict__ mag,
                   const float* __restrict__ cosp,
                   const float* __restrict__ sinp,
                   const float* __restrict__ window,
                   float* __restrict__ out) {
    extern __shared__ float smem[];
    float*  fbuf  = smem + SM_FBUF;
    float2* tw    = reinterpret_cast<float2*>(smem + SM_TW);
    float*  win_s = smem + SM_WIN;
    float*  ienv  = smem + SM_IENV;

    const int tid  = threadIdx.x;
    const int w    = tid >> 5;
    const int lane = tid & 31;
    const int c    = blockIdx.x;
    const int b    = blockIdx.y;
    const int ft0  = G_HOPS * c - 1;

    // ---- tables ----
    for (int j = tid; j < 512; j += THREADS) tw[j] = g_tw[j];
    for (int j = tid; j < 1024; j += THREADS)
        win_s[SKEW(j)] = window[j] * (1.0f / 1024.0f);
    {   // interior inverse envelope: env(s) depends only on s mod 256
        float e = 0.0f;
#pragma unroll
        for (int q = 0; q < 4; q++) {
            float wv = window[tid + 256 * q];
            e += wv * wv;
        }
        ienv[tid] = 1.0f / (e + 1e-11f);
    }
    __syncthreads();

    const size_t bbase = (size_t)b * NFREQ * NT;

    // ---- hoisted per-thread FFT twiddles ----
    const int pr  = w >> 1;                          // pair id 0..3
    const int hb  = w & 1;                           // half within pair
    const int n64 = 2 * (__brev(lane) >> 27) + hb;   // output index 0..63
    const float2 W64l  = tw[16 * lane];              // e^{2*pi*i*lane/64}
    const float2 Wbase = tw[2 * n64];                // e^{2*pi*i*n64/512}

    // ---- two rounds: stage up to 8 Z-spectra, FFT them ----
#pragma unroll 1
    for (int r = 0; r < 2; r++) {
        // stage: thread handles conjugate pair (k, 512-k) for one frame slot
        {
            const int t_off = tid & 7;
            const int slot = r * 8 + t_off;
            const int f_off = tid >> 3;              // 0..31
            const int t = ft0 + slot;
            if (slot < NFRAMES && t >= 0 && t < NT) {
                float* zb = fbuf + slot * ROW;
                const float* pm = mag  + bbase + (size_t)t;
                const float* pc = cosp + bbase + (size_t)t;
                const float* ps = sinp + bbase + (size_t)t;
                int ka = f_off * NT;
                int kb = (512 - f_off) * NT;
#pragma unroll 4
                for (int i = 0; i < 8; i++) {
                    const int k  = f_off + 32 * i;   // 0..255
                    const int km = 512 - k;
                    float ma = pm[ka], ca = pc[ka], sa = ps[ka];
                    float mb = pm[kb], cb = pc[kb], sb = ps[kb];
                    float ax = ma * ca, ay = ma * sa;
                    float bx = mb * cb, by = mb * sb;
                    if (k == 0) { ay = 0.0f; by = 0.0f; }
                    float2 W = tw[k];
                    float qx = ax - bx, qy = ay + by;
                    float S = ax + bx, D = ay - by;
                    float T = W.x * qy + W.y * qx;
                    float U = W.x * qx - W.y * qy;
                    {   // Z[k]
                        int a0 = ZBLK8 * (k >> 3) + 2 * (k & 7);
                        *reinterpret_cast<float2*>(zb + a0) = make_float2(S - T, D + U);
                    }
                    if (k > 0) {   // Z[512-k]
                        int a1 = ZBLK8 * (km >> 3) + 2 * (km & 7);
                        *reinterpret_cast<float2*>(zb + a1) = make_float2(S + T, U - D);
                    }
                    ka += 32 * NT;
                    kb -= 32 * NT;
                }
                if (f_off == 0) {   // k = 256 (self-conjugate)
                    const int kc = 256 * NT;
                    float ma = pm[kc], ca = pc[kc], sa = ps[kc];
                    *reinterpret_cast<float2*>(zb + ZBLK8 * 32) =
                        make_float2(2.0f * ma * ca, -2.0f * ma * sa);
                }
            }
        }
        __syncthreads();

        // FFT: pair pr handles slots r*8+pr and r*8+pr+4
#pragma unroll 1
        for (int sidx = 0; sidx < 2; sidx++) {
            const int slot = r * 8 + pr + 4 * sidx;
            const int t = ft0 + slot;
            if (slot >= NFRAMES || t < 0 || t >= NT) continue;
            float* frow = fbuf + slot * ROW;

            // h=32 butterfly of the 64-pt inverse DIF, straight from SMEM:
            // self block u = 32*hb + lane, partner block u^32.
            float2 v[8];
            {
                const float2* zlo = reinterpret_cast<const float2*>(frow) + 9 * lane;
                const float2* zhi = reinterpret_cast<const float2*>(frow) + 9 * (lane + 32);
                if (hb == 0) {
#pragma unroll
                    for (int j = 0; j < 8; j++) {
                        float2 a = zlo[j], q = zhi[j];
                        v[j] = make_float2(a.x + q.x, a.y + q.y);
                    }
                } else {
#pragma unroll
                    for (int j = 0; j < 8; j++) {
                        float2 a = zlo[j], q = zhi[j];
                        float2 d = make_float2(a.x - q.x, a.y - q.y);
                        v[j] = cmul(d, W64l);
                    }
                }
            }

            // remaining 5 stages: 32-pt inverse DIF over lanes (per reg)
#pragma unroll
            for (int s = 0; s < 5; s++) {
                const int h = 16 >> s;
                const float wc = W32C[(lane & (h - 1)) << s];
                const float ws = W32S[(lane & (h - 1)) << s];
                const bool hi = (lane & h) != 0;
#pragma unroll
                for (int j = 0; j < 8; j++) {
                    float px = __shfl_xor_sync(0xffffffffu, v[j].x, h);
                    float py = __shfl_xor_sync(0xffffffffu, v[j].y, h);
                    float2 rr;
                    if (hi) {
                        float dx = px - v[j].x;
                        float dy = py - v[j].y;
                        rr = make_float2(dx * wc - dy * ws, dx * ws + dy * wc);
                    } else {
                        rr = make_float2(v[j].x + px, v[j].y + py);
                    }
                    v[j] = rr;
                }
            }

            // mid twiddle: v[j] *= W512^{j*n64} via recurrence
            {
                float2 Wc = Wbase;
#pragma unroll
                for (int j = 1; j < 8; j++) {
                    v[j] = cmul(v[j], Wc);
                    Wc = cmul(Wc, Wbase);
                }
            }

            // 8-pt register inverse FFT over j -> n2 (bit-reversed in regs)
            ifft8_dif(v);

            // pair barrier: both warps must finish reading Z before overwrite
            asm volatile("bar.sync %0, %1;" :: "r"(pr + 1), "r"(64));

            // windowed store: reg rg holds y[n64 + 64*BR3[rg]] ->
            // samples n = 2*n64 + 128*BR3[rg] (+1)
#pragma unroll
            for (int rg = 0; rg < 8; rg++) {
                const int n  = 2 * n64 + 128 * BR3[rg];
                const int ni = SKEW(n);              // even
                float2 wv = *reinterpret_cast<const float2*>(win_s + ni);
                *reinterpret_cast<float2*>(frow + ni) =
                    make_float2(v[rg].x * wv.x, v[rg].y * wv.y);
            }
        }
        __syncthreads();
    }

    // ---- overlap-add + normalize + trim ----
    const int j0 = c * CHUNK;
    float* outb = out + (size_t)b * OUT_PER_B;

    if (c > 0 && c < NCHUNK - 1) {
        // interior: exactly 4 frames per sample, env from table; 2 samples/thread
#pragma unroll 1
        for (int i = 0; i < (CHUNK / 2 + 255) / 256; i++) {
            const int p = i * 256 + tid;
            if (p >= CHUNK / 2) break;
            const int j = j0 + 2 * p;
            const int s = j + NFFT / 2;
            const int t0 = (s - 768) >> 8;
            const int r0 = t0 - ft0;
            const int nb = s - (t0 << 8);            // [768,1022], even
            float2 acc = make_float2(0.0f, 0.0f);
#pragma unroll
            for (int q = 0; q < 4; q++) {
                const int n  = nb - (q << 8);
                const int ni = SKEW(n);
                float2 f = *reinterpret_cast<const float2*>(fbuf + (r0 + q) * ROW + ni);
                acc.x += f.x; acc.y += f.y;
            }
            const int m = s & 255;                   // even
            float2 o = make_float2(acc.x * ienv[m], acc.y * ienv[m + 1]);
            *reinterpret_cast<float2*>(outb + j) = o;
        }
    } else {
        // edge blocks: honest env accumulation (win_s is w/1024 -> rescale)
#pragma unroll 1
        for (int i = 0; i < G_HOPS; i++) {
            const int j = j0 + i * HOP + tid;
            if (j >= OUT_PER_B) break;
            const int s = j + NFFT / 2;
            int thi = s >> 8; if (thi > NT - 1) thi = NT - 1;
            int tlo = (s - 768) >> 8; if (tlo < 0) tlo = 0;
            float acc = 0.0f, env = 0.0f;
#pragma unroll 4
            for (int t = tlo; t <= thi; t++) {
                const int n  = s - (t << 8);
                const int ni = SKEW(n);
                acc += fbuf[(t - ft0) * ROW + ni];
                float wv = win_s[ni];
                env += wv * wv;
            }
            outb[j] = acc / (env * 1048576.0f + 1e-11f);
        }
    }
}

// ---------------------------------------------------------------------------
extern "C" void kernel_launch(void* const* d_in, const int* in_sizes, int n_in,
                              void* d_out, int out_size) {
    const float* mag    = (const float*)d_in[0];
    const float* cosp   = (const float*)d_in[1];
    const float* sinp   = (const float*)d_in[2];
    const float* window = (const float*)d_in[3];
    float* out = (float*)d_out;

    cudaFuncSetAttribute(istft_fused_kernel,
                         cudaFuncAttributeMaxDynamicSharedMemorySize, SMEM_BYTES);

    tw_init_kernel<<<2, 256>>>();

    dim3 grid(NCHUNK, NB);   // 364 x 16
    istft_fused_kernel<<<grid, THREADS, SMEM_BYTES>>>(mag, cosp, sinp, window, out);
}

// round 16
// speedup vs baseline: 1.6506x; 1.6506x over previous
#include <cuda_runtime.h>
#include <cstdint>

// Problem constants
#define NB     16
#define NFREQ  513
#define NT     4000
#define NFFT   1024
#define HOP    256
#define OUT_PER_B (3999 * 256)   // 1023744

#define THREADS 256
#define G_HOPS  19               // output hops per block
#define NFRAMES 22               // frames per block (19 + 3 halo)
#define CHUNK   (G_HOPS * HOP)   // 4864
#define NCHUNK  ((OUT_PER_B + CHUNK - 1) / CHUNK)   // 211

#define ROW     1156             // frame row stride (floats), %4==0
#define ZBLK    36               // words per 16-complex Z block (float4-aligned)

// 16B-preserving skew: +4 floats per 64-float block
#define SKEW(n) ((n) + (((n) >> 6) << 2))

// SMEM layout (floats)
#define SM_FBUF 0
#define SM_TW   (SM_FBUF + NFRAMES * ROW)           // 25432
#define SM_WIN  (SM_TW + 1024)                      // 26456
#define SM_IENV (SM_WIN + 1088)                     // 27544
#define SM_FLOATS (SM_IENV + 256)                   // 27800
#define SMEM_BYTES (SM_FLOATS * 4)                  // 111200 B -> 2 blocks/SM

// Twiddle table e^{+2*pi*i*j/1024}, j = 0..511
__device__ float2 g_tw[512];

// e^{+2*pi*i*j/32}
__constant__ float W32C[32] = {
     1.000000000f,  0.980785280f,  0.923879533f,  0.831469612f,
     0.707106781f,  0.555570233f,  0.382683432f,  0.195090322f,
     0.000000000f, -0.195090322f, -0.382683432f, -0.555570233f,
    -0.707106781f, -0.831469612f, -0.923879533f, -0.980785280f,
    -1.000000000f, -0.980785280f, -0.923879533f, -0.831469612f,
    -0.707106781f, -0.555570233f, -0.382683432f, -0.195090322f,
     0.000000000f,  0.195090322f,  0.382683432f,  0.555570233f,
     0.707106781f,  0.831469612f,  0.923879533f,  0.980785280f
};
__constant__ float W32S[32] = {
     0.000000000f,  0.195090322f,  0.382683432f,  0.555570233f,
     0.707106781f,  0.831469612f,  0.923879533f,  0.980785280f,
     1.000000000f,  0.980785280f,  0.923879533f,  0.831469612f,
     0.707106781f,  0.555570233f,  0.382683432f,  0.195090322f,
     0.000000000f, -0.195090322f, -0.382683432f, -0.555570233f,
    -0.707106781f, -0.831469612f, -0.923879533f, -0.980785280f,
    -1.000000000f, -0.980785280f, -0.923879533f, -0.831469612f,
    -0.707106781f, -0.555570233f, -0.382683432f, -0.195090322f
};

__global__ void tw_init_kernel() {
    int j = blockIdx.x * 256 + threadIdx.x;
    if (j < 512) {
        float s, c;
        sincospif((float)j * (1.0f / 512.0f), &s, &c);   // 2*pi*j/1024
        g_tw[j] = make_float2(c, s);
    }
}

__device__ __forceinline__ float2 cmul(float2 a, float2 b) {
    return make_float2(a.x * b.x - a.y * b.y, a.x * b.y + a.y * b.x);
}

// ---------------------------------------------------------------------------
// 16-point inverse DFT in registers (radix-4 x radix-4), natural in/out.
// ---------------------------------------------------------------------------
__device__ __forceinline__ void ifft16(float2 v[16]) {
    float2 g[16];
#pragma unroll
    for (int j1 = 0; j1 < 4; j1++) {
        float2 a = v[j1], b = v[j1 + 4], c = v[j1 + 8], d = v[j1 + 12];
        float t0x = a.x + c.x, t0y = a.y + c.y;
        float t1x = a.x - c.x, t1y = a.y - c.y;
        float t2x = b.x + d.x, t2y = b.y + d.y;
        float t3x = b.x - d.x, t3y = b.y - d.y;
        g[j1 * 4 + 0] = make_float2(t0x + t2x, t0y + t2y);
        g[j1 * 4 + 1] = make_float2(t1x - t3y, t1y + t3x);
        g[j1 * 4 + 2] = make_float2(t0x - t2x, t0y - t2y);
        g[j1 * 4 + 3] = make_float2(t1x + t3y, t1y - t3x);
    }
#pragma unroll
    for (int j1 = 1; j1 < 4; j1++) {
#pragma unroll
        for (int m2 = 1; m2 < 4; m2++) {
            float wc = W32C[2 * j1 * m2];
            float ws = W32S[2 * j1 * m2];
            float2 x = g[j1 * 4 + m2];
            g[j1 * 4 + m2] = make_float2(x.x * wc - x.y * ws, x.x * ws + x.y * wc);
        }
    }
#pragma unroll
    for (int m2 = 0; m2 < 4; m2++) {
        float2 a = g[m2], b = g[4 + m2], c = g[8 + m2], d = g[12 + m2];
        float t0x = a.x + c.x, t0y = a.y + c.y;
        float t1x = a.x - c.x, t1y = a.y - c.y;
        float t2x = b.x + d.x, t2y = b.y + d.y;
        float t3x = b.x - d.x, t3y = b.y - d.y;
        v[m2 + 0]  = make_float2(t0x + t2x, t0y + t2y);
        v[m2 + 4]  = make_float2(t1x - t3y, t1y + t3x);
        v[m2 + 8]  = make_float2(t0x - t2x, t0y - t2y);
        v[m2 + 12] = make_float2(t1x + t3y, t1y - t3x);
    }
}

// ---------------------------------------------------------------------------
// Fused kernel. grid = (NCHUNK, NB), block = 256 (8 warps), 2 blocks/SM.
// Single staging phase into fbuf rows (aliased), warp-owns-frame FFT in place.
// ---------------------------------------------------------------------------
__global__ void __launch_bounds__(THREADS, 2)
istft_fused_kernel(const float* __restrict__ mag,
                   const float* __restrict__ cosp,
                   const float* __restrict__ sinp,
                   const float* __restrict__ window,
                   float* __restrict__ out) {
    extern __shared__ float smem[];
    float*  fbuf  = smem + SM_FBUF;
    float2* tw    = reinterpret_cast<float2*>(smem + SM_TW);
    float*  win_s = smem + SM_WIN;
    float*  ienv  = smem + SM_IENV;

    const int tid  = threadIdx.x;
    const int w    = tid >> 5;
    const int lane = tid & 31;
    const int c    = blockIdx.x;
    const int b    = blockIdx.y;
    const int ft0  = G_HOPS * c - 1;

    // ---- tables ----
    for (int j = tid; j < 512; j += THREADS) tw[j] = g_tw[j];
    for (int j = tid; j < 1024; j += THREADS)
        win_s[SKEW(j)] = window[j] * (1.0f / 1024.0f);
    {   // interior inverse envelope: env(s) depends only on s mod 256
        float e = 0.0f;
#pragma unroll
        for (int q = 0; q < 4; q++) {
            float wv = window[tid + 256 * q];
            e += wv * wv;
        }
        ienv[tid] = 1.0f / (e + 1e-11f);
    }
    __syncthreads();

    const size_t bbase = (size_t)b * NFREQ * NT;

    // ---- single staging phase: all NFRAMES Z-spectra into fbuf rows ----
    // task = f_off * NFRAMES + slot (f-major keeps t-contiguous coalescing)
#pragma unroll 1
    for (int task = tid; task < 32 * NFRAMES; task += THREADS) {
        const int f_off = task / NFRAMES;
        const int slot  = task - f_off * NFRAMES;
        const int t = ft0 + slot;
        if (t < 0 || t >= NT) continue;
        float* zb = fbuf + slot * ROW;
        const float* pm = mag  + bbase + (size_t)t;
        const float* pc = cosp + bbase + (size_t)t;
        const float* ps = sinp + bbase + (size_t)t;
        int ka = f_off * NT;
        int kb = (512 - f_off) * NT;
#pragma unroll 4
        for (int i = 0; i < 8; i++) {
            const int k  = f_off + 32 * i;   // 0..255
            const int km = 512 - k;
            float ma = pm[ka], ca = pc[ka], sa = ps[ka];
            float mb = pm[kb], cb = pc[kb], sb = ps[kb];
            float ax = ma * ca, ay = ma * sa;
            float bx = mb * cb, by = mb * sb;
            if (k == 0) { ay = 0.0f; by = 0.0f; }
            float2 W = tw[k];
            float qx = ax - bx, qy = ay + by;
            float S = ax + bx, D = ay - by;
            float T = W.x * qy + W.y * qx;
            float U = W.x * qx - W.y * qy;
            {   // Z[k]
                int a0 = ZBLK * (k >> 4) + 2 * (k & 15);
                *reinterpret_cast<float2*>(zb + a0) = make_float2(S - T, D + U);
            }
            if (k > 0) {   // Z[512-k]
                int a1 = ZBLK * (km >> 4) + 2 * (km & 15);
                *reinterpret_cast<float2*>(zb + a1) = make_float2(S + T, U - D);
            }
            ka += 32 * NT;
            kb -= 32 * NT;
        }
        if (f_off == 0) {   // k = 256 (self-conjugate)
            const int kc = 256 * NT;
            float ma = pm[kc], ca = pc[kc], sa = ps[kc];
            *reinterpret_cast<float2*>(zb + ZBLK * 16) =
                make_float2(2.0f * ma * ca, -2.0f * ma * sa);
        }
    }
    __syncthreads();

    // ---- FFT phase: warp w handles slots w, w+8, w+16 ----
    const int n1 = __brev(lane) >> 27;               // bitrev5(lane)
    const float2 Wb_mid = tw[2 * n1];                // e^{2*pi*i*n1/512}

#pragma unroll 1
    for (int slot = w; slot < NFRAMES; slot += 8) {
        const int t = ft0 + slot;
        if (t < 0 || t >= NT) continue;
        float* frow = fbuf + slot * ROW;

        // load 16 contiguous complex per lane: k = 16*lane + k2
        float2 v[16];
        {
            const float4* zr = reinterpret_cast<const float4*>(frow + ZBLK * lane);
#pragma unroll
            for (int j = 0; j < 8; j++) {
                float4 q = zr[j];
                v[2 * j]     = make_float2(q.x, q.y);
                v[2 * j + 1] = make_float2(q.z, q.w);
            }
        }

        // cross-lane 32-pt inverse DIF over k1 = lane; output lane holds n1
#pragma unroll
        for (int s = 0; s < 5; s++) {
            const int h = 16 >> s;
            const float wc = W32C[(lane & (h - 1)) << s];
            const float ws = W32S[(lane & (h - 1)) << s];
            const bool hi = (lane & h) != 0;
#pragma unroll
            for (int k2 = 0; k2 < 16; k2++) {
                float px = __shfl_xor_sync(0xffffffffu, v[k2].x, h);
                float py = __shfl_xor_sync(0xffffffffu, v[k2].y, h);
                float2 rr;
                if (hi) {
                    float dx = px - v[k2].x;
                    float dy = py - v[k2].y;
                    rr = make_float2(dx * wc - dy * ws, dx * ws + dy * wc);
                } else {
                    rr = make_float2(v[k2].x + px, v[k2].y + py);
                }
                v[k2] = rr;
            }
        }

        // mid twiddle: v[k2] *= W512^{k2*n1} via power recurrence
        {
            float2 Wc = Wb_mid;
#pragma unroll
            for (int k2 = 1; k2 < 16; k2++) {
                v[k2] = cmul(v[k2], Wc);
                Wc = cmul(Wc, Wb_mid);
            }
        }

        // 16-pt register IDFT over k2 -> n2 (natural order)
        ifft16(v);

        // windowed store: lane n1 owns samples n = 2*n1 + 64*n2 (+1)
#pragma unroll
        for (int n2 = 0; n2 < 16; n2++) {
            const int n  = 2 * n1 + (n2 << 6);
            const int ni = SKEW(n);              // = 2*n1 + 68*n2, even
            float2 wv = *reinterpret_cast<const float2*>(win_s + ni);
            *reinterpret_cast<float2*>(frow + ni) =
                make_float2(v[n2].x * wv.x, v[n2].y * wv.y);
        }
    }
    __syncthreads();

    // ---- overlap-add + normalize + trim ----
    const int j0 = c * CHUNK;
    float* outb = out + (size_t)b * OUT_PER_B;

    if (c > 0 && c < NCHUNK - 1) {
        // interior: exactly 4 frames per sample, env from table; 4 samples/thread
#pragma unroll 1
        for (int i = 0; i < (CHUNK / 4 + 255) / 256; i++) {
            const int p = i * 256 + tid;
            if (p >= CHUNK / 4) break;
            const int j = j0 + 4 * p;
            const int s = j + NFFT / 2;
            const int t0 = (s - 768) >> 8;
            const int r0 = t0 - ft0;
            const int nb = s - (t0 << 8);            // [768,1020], %4==0
            float4 acc = make_float4(0.f, 0.f, 0.f, 0.f);
#pragma unroll
            for (int q = 0; q < 4; q++) {
                const int n  = nb - (q << 8);
                const int ni = SKEW(n);              // %4==0
                float4 f = *reinterpret_cast<const float4*>(fbuf + (r0 + q) * ROW + ni);
                acc.x += f.x; acc.y += f.y; acc.z += f.z; acc.w += f.w;
            }
            const int m = s & 255;                   // %4==0
            float4 e = *reinterpret_cast<const float4*>(ienv + m);
            float4 o;
            o.x = acc.x * e.x; o.y = acc.y * e.y;
            o.z = acc.z * e.z; o.w = acc.w * e.w;
            *reinterpret_cast<float4*>(outb + j) = o;
        }
    } else {
        // edge blocks: honest env accumulation (win_s is w/1024 -> rescale)
#pragma unroll 1
        for (int i = 0; i < G_HOPS; i++) {
            const int j = j0 + i * HOP + tid;
            if (j >= OUT_PER_B) break;
            const int s = j + NFFT / 2;
            int thi = s >> 8; if (thi > NT - 1) thi = NT - 1;
            int tlo = (s - 768) >> 8; if (tlo < 0) tlo = 0;
            float acc = 0.0f, env = 0.0f;
#pragma unroll 4
            for (int t = tlo; t <= thi; t++) {
                const int n  = s - (t << 8);
                const int ni = SKEW(n);
                acc += fbuf[(t - ft0) * ROW + ni];
                float wv = win_s[ni];
                env += wv * wv;
            }
            outb[j] = acc / (env * 1048576.0f + 1e-11f);
        }
    }
}

// ---------------------------------------------------------------------------
extern "C" void kernel_launch(void* const* d_in, const int* in_sizes, int n_in,
                              void* d_out, int out_size) {
    const float* mag    = (const float*)d_in[0];
    const float* cosp   = (const float*)d_in[1];
    const float* sinp   = (const float*)d_in[2];
    const float* window = (const float*)d_in[3];
    float* out = (float*)d_out;

    cudaFuncSetAttribute(istft_fused_kernel,
                         cudaFuncAttributeMaxDynamicSharedMemorySize, SMEM_BYTES);

    tw_init_kernel<<<2, 256>>>();

    dim3 grid(NCHUNK, NB);   // 211 x 16
    istft_fused_kernel<<<grid, THREADS, SMEM_BYTES>>>(mag, cosp, sinp, window, out);
}

// round 17
// speedup vs baseline: 1.7226x; 1.0436x over previous
#include <cuda_runtime.h>
#include <cstdint>

// Problem constants
#define NB     16
#define NFREQ  513
#define NT     4000
#define NFFT   1024
#define HOP    256
#define OUT_PER_B (3999 * 256)   // 1023744

#define THREADS 512
#define G_HOPS  43               // output hops per block
#define NFRAMES 46               // frames per block (43 + 3 halo)
#define CHUNK   (G_HOPS * HOP)   // 11008
#define NCHUNK  (OUT_PER_B / CHUNK)   // 93 (exact)

#define ROW     1156             // frame row stride (floats), %4==0
#define ZBLK    36               // words per 16-complex Z block (float4-aligned)

// 16B-preserving skew: +4 floats per 64-float block
#define SKEW(n) ((n) + (((n) >> 6) << 2))

// SMEM layout (floats)
#define SM_FBUF 0
#define SM_TW   (SM_FBUF + NFRAMES * ROW)           // 53176
#define SM_WIN  (SM_TW + 1024)                      // 54200
#define SM_IENV (SM_WIN + 1088)                     // 55288
#define SM_FLOATS (SM_IENV + 256)                   // 55544
#define SMEM_BYTES (SM_FLOATS * 4)                  // 222176 B -> 1 block/SM

// Twiddle table e^{+2*pi*i*j/1024}, j = 0..511
__device__ float2 g_tw[512];

// e^{+2*pi*i*j/32}
__constant__ float W32C[32] = {
     1.000000000f,  0.980785280f,  0.923879533f,  0.831469612f,
     0.707106781f,  0.555570233f,  0.382683432f,  0.195090322f,
     0.000000000f, -0.195090322f, -0.382683432f, -0.555570233f,
    -0.707106781f, -0.831469612f, -0.923879533f, -0.980785280f,
    -1.000000000f, -0.980785280f, -0.923879533f, -0.831469612f,
    -0.707106781f, -0.555570233f, -0.382683432f, -0.195090322f,
     0.000000000f,  0.195090322f,  0.382683432f,  0.555570233f,
     0.707106781f,  0.831469612f,  0.923879533f,  0.980785280f
};
__constant__ float W32S[32] = {
     0.000000000f,  0.195090322f,  0.382683432f,  0.555570233f,
     0.707106781f,  0.831469612f,  0.923879533f,  0.980785280f,
     1.000000000f,  0.980785280f,  0.923879533f,  0.831469612f,
     0.707106781f,  0.555570233f,  0.382683432f,  0.195090322f,
     0.000000000f, -0.195090322f, -0.382683432f, -0.555570233f,
    -0.707106781f, -0.831469612f, -0.923879533f, -0.980785280f,
    -1.000000000f, -0.980785280f, -0.923879533f, -0.831469612f,
    -0.707106781f, -0.555570233f, -0.382683432f, -0.195090322f
};

__global__ void tw_init_kernel() {
    int j = blockIdx.x * 256 + threadIdx.x;
    if (j < 512) {
        float s, c;
        sincospif((float)j * (1.0f / 512.0f), &s, &c);   // 2*pi*j/1024
        g_tw[j] = make_float2(c, s);
    }
}

__device__ __forceinline__ float2 cmul(float2 a, float2 b) {
    return make_float2(a.x * b.x - a.y * b.y, a.x * b.y + a.y * b.x);
}

// ---------------------------------------------------------------------------
// 16-point inverse DFT in registers (radix-4 x radix-4), natural in/out.
// ---------------------------------------------------------------------------
__device__ __forceinline__ void ifft16(float2 v[16]) {
    float2 g[16];
#pragma unroll
    for (int j1 = 0; j1 < 4; j1++) {
        float2 a = v[j1], b = v[j1 + 4], c = v[j1 + 8], d = v[j1 + 12];
        float t0x = a.x + c.x, t0y = a.y + c.y;
        float t1x = a.x - c.x, t1y = a.y - c.y;
        float t2x = b.x + d.x, t2y = b.y + d.y;
        float t3x = b.x - d.x, t3y = b.y - d.y;
        g[j1 * 4 + 0] = make_float2(t0x + t2x, t0y + t2y);
        g[j1 * 4 + 1] = make_float2(t1x - t3y, t1y + t3x);
        g[j1 * 4 + 2] = make_float2(t0x - t2x, t0y - t2y);
        g[j1 * 4 + 3] = make_float2(t1x + t3y, t1y - t3x);
    }
#pragma unroll
    for (int j1 = 1; j1 < 4; j1++) {
#pragma unroll
        for (int m2 = 1; m2 < 4; m2++) {
            float wc = W32C[2 * j1 * m2];
            float ws = W32S[2 * j1 * m2];
            float2 x = g[j1 * 4 + m2];
            g[j1 * 4 + m2] = make_float2(x.x * wc - x.y * ws, x.x * ws + x.y * wc);
        }
    }
#pragma unroll
    for (int m2 = 0; m2 < 4; m2++) {
        float2 a = g[m2], b = g[4 + m2], c = g[8 + m2], d = g[12 + m2];
        float t0x = a.x + c.x, t0y = a.y + c.y;
        float t1x = a.x - c.x, t1y = a.y - c.y;
        float t2x = b.x + d.x, t2y = b.y + d.y;
        float t3x = b.x - d.x, t3y = b.y - d.y;
        v[m2 + 0]  = make_float2(t0x + t2x, t0y + t2y);
        v[m2 + 4]  = make_float2(t1x - t3y, t1y + t3x);
        v[m2 + 8]  = make_float2(t0x - t2x, t0y - t2y);
        v[m2 + 12] = make_float2(t1x + t3y, t1y - t3x);
    }
}

// ---------------------------------------------------------------------------
// Fused kernel. grid = (NCHUNK, NB), block = 512 (16 warps), 1 block/SM.
// Single staging phase into fbuf rows (aliased), warp-owns-frame FFT in place.
// ---------------------------------------------------------------------------
__global__ void __launch_bounds__(THREADS, 1)
istft_fused_kernel(const float* __restrict__ mag,
                   const float* __restrict__ cosp,
                   const float* __restrict__ sinp,
                   const float* __restrict__ window,
                   float* __restrict__ out) {
    extern __shared__ float smem[];
    float*  fbuf  = smem + SM_FBUF;
    float2* tw    = reinterpret_cast<float2*>(smem + SM_TW);
    float*  win_s = smem + SM_WIN;
    float*  ienv  = smem + SM_IENV;

    const int tid  = threadIdx.x;
    const int w    = tid >> 5;
    const int lane = tid & 31;
    const int c    = blockIdx.x;
    const int b    = blockIdx.y;
    const int ft0  = G_HOPS * c - 1;

    // ---- tables ----
    for (int j = tid; j < 512; j += THREADS) tw[j] = g_tw[j];
    for (int j = tid; j < 1024; j += THREADS)
        win_s[SKEW(j)] = window[j] * (1.0f / 1024.0f);
    if (tid < 256) {   // interior inverse envelope: env(s) depends only on s mod 256
        float e = 0.0f;
#pragma unroll
        for (int q = 0; q < 4; q++) {
            float wv = window[tid + 256 * q];
            e += wv * wv;
        }
        ienv[tid] = 1.0f / (e + 1e-11f);
    }
    __syncthreads();

    const size_t bbase = (size_t)b * NFREQ * NT;

    // ---- single staging phase: all NFRAMES Z-spectra into fbuf rows ----
    // task = f_off * NFRAMES + slot (f-major keeps t-contiguous coalescing)
#pragma unroll 1
    for (int task = tid; task < 32 * NFRAMES; task += THREADS) {
        const int f_off = task / NFRAMES;
        const int slot  = task - f_off * NFRAMES;
        const int t = ft0 + slot;
        if (t < 0 || t >= NT) continue;
        float* zb = fbuf + slot * ROW;
        const float* pm = mag  + bbase + (size_t)t;
        const float* pc = cosp + bbase + (size_t)t;
        const float* ps = sinp + bbase + (size_t)t;
        int ka = f_off * NT;
        int kb = (512 - f_off) * NT;
#pragma unroll 4
        for (int i = 0; i < 8; i++) {
            const int k  = f_off + 32 * i;   // 0..255
            const int km = 512 - k;
            float ma = pm[ka], ca = pc[ka], sa = ps[ka];
            float mb = pm[kb], cb = pc[kb], sb = ps[kb];
            float ax = ma * ca, ay = ma * sa;
            float bx = mb * cb, by = mb * sb;
            if (k == 0) { ay = 0.0f; by = 0.0f; }
            float2 W = tw[k];
            float qx = ax - bx, qy = ay + by;
            float S = ax + bx, D = ay - by;
            float T = W.x * qy + W.y * qx;
            float U = W.x * qx - W.y * qy;
            {   // Z[k]
                int a0 = ZBLK * (k >> 4) + 2 * (k & 15);
                *reinterpret_cast<float2*>(zb + a0) = make_float2(S - T, D + U);
            }
            if (k > 0) {   // Z[512-k]
                int a1 = ZBLK * (km >> 4) + 2 * (km & 15);
                *reinterpret_cast<float2*>(zb + a1) = make_float2(S + T, U - D);
            }
            ka += 32 * NT;
            kb -= 32 * NT;
        }
        if (f_off == 0) {   // k = 256 (self-conjugate)
            const int kc = 256 * NT;
            float ma = pm[kc], ca = pc[kc], sa = ps[kc];
            *reinterpret_cast<float2*>(zb + ZBLK * 16) =
                make_float2(2.0f * ma * ca, -2.0f * ma * sa);
        }
    }
    __syncthreads();

    // ---- FFT phase: warp w handles slots w, w+16, w+32 ----
    const int n1 = __brev(lane) >> 27;               // bitrev5(lane)
    const float2 Wb_mid = tw[2 * n1];                // e^{2*pi*i*n1/512}

#pragma unroll 1
    for (int slot = w; slot < NFRAMES; slot += 16) {
        const int t = ft0 + slot;
        if (t < 0 || t >= NT) continue;
        float* frow = fbuf + slot * ROW;

        // load 16 contiguous complex per lane: k = 16*lane + k2
        float2 v[16];
        {
            const float4* zr = reinterpret_cast<const float4*>(frow + ZBLK * lane);
#pragma unroll
            for (int j = 0; j < 8; j++) {
                float4 q = zr[j];
                v[2 * j]     = make_float2(q.x, q.y);
                v[2 * j + 1] = make_float2(q.z, q.w);
            }
        }

        // cross-lane 32-pt inverse DIF over k1 = lane; output lane holds n1
#pragma unroll
        for (int s = 0; s < 5; s++) {
            const int h = 16 >> s;
            const float wc = W32C[(lane & (h - 1)) << s];
            const float ws = W32S[(lane & (h - 1)) << s];
            const bool hi = (lane & h) != 0;
#pragma unroll
            for (int k2 = 0; k2 < 16; k2++) {
                float px = __shfl_xor_sync(0xffffffffu, v[k2].x, h);
                float py = __shfl_xor_sync(0xffffffffu, v[k2].y, h);
                float2 rr;
                if (hi) {
                    float dx = px - v[k2].x;
                    float dy = py - v[k2].y;
                    rr = make_float2(dx * wc - dy * ws, dx * ws + dy * wc);
                } else {
                    rr = make_float2(v[k2].x + px, v[k2].y + py);
                }
                v[k2] = rr;
            }
        }

        // mid twiddle: v[k2] *= W512^{k2*n1} via power recurrence
        {
            float2 Wc = Wb_mid;
#pragma unroll
            for (int k2 = 1; k2 < 16; k2++) {
                v[k2] = cmul(v[k2], Wc);
                Wc = cmul(Wc, Wb_mid);
            }
        }

        // 16-pt register IDFT over k2 -> n2 (natural order)
        ifft16(v);

        // windowed store: lane n1 owns samples n = 2*n1 + 64*n2 (+1)
#pragma unroll
        for (int n2 = 0; n2 < 16; n2++) {
            const int n  = 2 * n1 + (n2 << 6);
            const int ni = SKEW(n);              // = 2*n1 + 68*n2, even
            float2 wv = *reinterpret_cast<const float2*>(win_s + ni);
            *reinterpret_cast<float2*>(frow + ni) =
                make_float2(v[n2].x * wv.x, v[n2].y * wv.y);
        }
    }
    __syncthreads();

    // ---- overlap-add + normalize + trim ----
    const int j0 = c * CHUNK;
    float* outb = out + (size_t)b * OUT_PER_B;

    if (c > 0 && c < NCHUNK - 1) {
        // interior: exactly 4 frames per sample, env from table; 4 samples/thread
#pragma unroll 1
        for (int p = tid; p < CHUNK / 4; p += THREADS) {
            const int j = j0 + 4 * p;
            const int s = j + NFFT / 2;
            const int t0 = (s - 768) >> 8;
            const int r0 = t0 - ft0;
            const int nb = s - (t0 << 8);            // [768,1020], %4==0
            float4 acc = make_float4(0.f, 0.f, 0.f, 0.f);
#pragma unroll
            for (int q = 0; q < 4; q++) {
                const int n  = nb - (q << 8);
                const int ni = SKEW(n);              // %4==0
                float4 f = *reinterpret_cast<const float4*>(fbuf + (r0 + q) * ROW + ni);
                acc.x += f.x; acc.y += f.y; acc.z += f.z; acc.w += f.w;
            }
            const int m = s & 255;                   // %4==0
            float4 e = *reinterpret_cast<const float4*>(ienv + m);
            float4 o;
            o.x = acc.x * e.x; o.y = acc.y * e.y;
            o.z = acc.z * e.z; o.w = acc.w * e.w;
            *reinterpret_cast<float4*>(outb + j) = o;
        }
    } else {
        // edge blocks: honest env accumulation (win_s is w/1024 -> rescale)
#pragma unroll 1
        for (int p = tid; p < CHUNK; p += THREADS) {
            const int j = j0 + p;
            if (j >= OUT_PER_B) break;
            const int s = j + NFFT / 2;
            int thi = s >> 8; if (thi > NT - 1) thi = NT - 1;
            int tlo = (s - 768) >> 8; if (tlo < 0) tlo = 0;
            float acc = 0.0f, env = 0.0f;
#pragma unroll 4
            for (int t = tlo; t <= thi; t++) {
                const int n  = s - (t << 8);
                const int ni = SKEW(n);
                acc += fbuf[(t - ft0) * ROW + ni];
                float wv = win_s[ni];
                env += wv * wv;
            }
            outb[j] = acc / (env * 1048576.0f + 1e-11f);
        }
    }
}

// ---------------------------------------------------------------------------
extern "C" void kernel_launch(void* const* d_in, const int* in_sizes, int n_in,
                              void* d_out, int out_size) {
    const float* mag    = (const float*)d_in[0];
    const float* cosp   = (const float*)d_in[1];
    const float* sinp   = (const float*)d_in[2];
    const float* window = (const float*)d_in[3];
    float* out = (float*)d_out;

    cudaFuncSetAttribute(istft_fused_kernel,
                         cudaFuncAttributeMaxDynamicSharedMemorySize, SMEM_BYTES);

    tw_init_kernel<<<2, 256>>>();

    dim3 grid(NCHUNK, NB);   // 93 x 16 = 1488 blocks
    istft_fused_kernel<<<grid, THREADS, SMEM_BYTES>>>(mag, cosp, sinp, window, out);
}